// round 5
// baseline (speedup 1.0000x reference)
#include <cuda_runtime.h>
#include <cuda_fp16.h>
#include <math.h>

#define SDIM 2048
#define HDIM 2048
#define LNUM 2
#define ANUM 16
#define NLOGBLK 128

// K1 geometry: type-A (layer0 full) 128 blocks, type-B (layer1 recurrent) 128 blocks
#define NB_A 128
#define NB_B 128
#define R_A 4     // unit-groups per type-A block
#define R_B 4     // row-groups per type-B block
#define R_2 4     // unit-groups per K2 block

// Persistent scratch
__device__ __align__(16) float g_h0[2][HDIM];
__device__ __align__(16) float g_h1[2][HDIM];
__device__ __align__(16) float g_c[LNUM][HDIM];
__device__ __align__(16) float g_pre1[4 * HDIM];   // layer-1 recurrent partial preacts
__device__ __align__(16) float g_logits[SDIM];
__device__ __align__(16) float g_partial[NLOGBLK];
__device__ __align__(16) __half g_wih16[LNUM * 4 * HDIM * HDIM];
__device__ __align__(16) __half g_whh16[LNUM * 4 * HDIM * HDIM];
__device__ __align__(16) __half g_wout16[SDIM * HDIM];

__device__ __forceinline__ float sigmoidf_(float x) {
    return 1.0f / (1.0f + __expf(-x));
}

// Per-thread partial of dot(W[row,:], act) with act staged in split smem arrays
// (s0[p]=vec4[2p], s1[p]=vec4[2p+1] -> conflict-free LDS.128).
__device__ __forceinline__ float rowdot16(
    const __half* __restrict__ W, int row,
    const float4* __restrict__ s0, const float4* __restrict__ s1, int lane)
{
    const uint4* __restrict__ w4 = (const uint4*)W + (size_t)row * (HDIM / 8);
    float acc0 = 0.f, acc1 = 0.f, acc2 = 0.f, acc3 = 0.f;
    uint4 w[8];
    #pragma unroll
    for (int k = 0; k < 8; k++) w[k] = w4[lane + k * 32];
    #pragma unroll
    for (int k = 0; k < 8; k++) {
        const __half2* hp = reinterpret_cast<const __half2*>(&w[k]);
        float4 a0 = s0[lane + k * 32];
        float4 a1 = s1[lane + k * 32];
        float2 f0 = __half22float2(hp[0]);
        float2 f1 = __half22float2(hp[1]);
        float2 f2 = __half22float2(hp[2]);
        float2 f3 = __half22float2(hp[3]);
        acc0 = fmaf(f0.x, a0.x, acc0); acc1 = fmaf(f0.y, a0.y, acc1);
        acc2 = fmaf(f1.x, a0.z, acc2); acc3 = fmaf(f1.y, a0.w, acc3);
        acc0 = fmaf(f2.x, a1.x, acc0); acc1 = fmaf(f2.y, a1.y, acc1);
        acc2 = fmaf(f3.x, a1.z, acc2); acc3 = fmaf(f3.y, a1.w, acc3);
    }
    return (acc0 + acc1) + (acc2 + acc3);
}

// ---------------------------------------------------------------------------
// K1: merged per-step kernel (steps 1..A-1).
// Blocks [0, NB_A): layer-0 full gates, input = inline softmax of prev logits.
// Blocks [NB_A, NB_A+NB_B): layer-1 recurrent partials -> g_pre1.
// Grid = 256 blocks x 512 threads: single co-resident wave.
// ---------------------------------------------------------------------------
__global__ void __launch_bounds__(512) step_k1(
    const __half* __restrict__ Wih0, const __half* __restrict__ Whh0,
    const __half* __restrict__ Whh1,
    const float* __restrict__ bih0, const float* __restrict__ bhh0,
    const float* __restrict__ bih1, const float* __restrict__ bhh1,
    const float* __restrict__ logits, const float* __restrict__ partials,
    float* __restrict__ out_prev,
    const float* __restrict__ h0_in, float* __restrict__ h0_out,
    const float* __restrict__ h1_in,
    float* __restrict__ c0, float* __restrict__ pre1)
{
    __shared__ float4 s_a0[256], s_a1[256], s_b0[256], s_b1[256];
    __shared__ float s_g[4][4];
    __shared__ float s_inv;

    const int t    = threadIdx.x;
    const int warp = t >> 5;
    const int lane = t & 31;

    if (blockIdx.x < NB_A) {
        // ----- layer 0: full gates + inline softmax input -----
        if (warp == 0) {
            float s = 0.0f;
            #pragma unroll
            for (int j = 0; j < 4; j++) s += partials[lane + j * 32];
            #pragma unroll
            for (int o = 16; o > 0; o >>= 1)
                s += __shfl_xor_sync(0xffffffffu, s, o);
            if (lane == 0) s_inv = 1.0f / s;
        }
        __syncthreads();
        {
            const float inv = s_inv;
            float4 lg = ((const float4*)logits)[t];
            float4 v;
            v.x = __expf(lg.x) * inv;
            v.y = __expf(lg.y) * inv;
            v.z = __expf(lg.z) * inv;
            v.w = __expf(lg.w) * inv;
            if (blockIdx.x == 0) ((float4*)out_prev)[t] = v;
            ((t & 1) ? s_a1 : s_a0)[t >> 1] = v;
            float4 hv = ((const float4*)h0_in)[t];
            ((t & 1) ? s_b1 : s_b0)[t >> 1] = hv;
        }
        __syncthreads();

        const int ulocal = warp >> 2;
        const int gate   = warp & 3;

        #pragma unroll
        for (int i = 0; i < R_A; i++) {
            const int unit = blockIdx.x * (4 * R_A) + i * 4 + ulocal;
            const int row  = gate * HDIM + unit;
            float acc = rowdot16(Wih0, row, s_a0, s_a1, lane)
                      + rowdot16(Whh0, row, s_b0, s_b1, lane);
            #pragma unroll
            for (int o = 16; o > 0; o >>= 1)
                acc += __shfl_xor_sync(0xffffffffu, acc, o);
            if (lane == 0)
                s_g[ulocal][gate] = acc + bih0[row] + bhh0[row];
            __syncthreads();
            if (t < 4) {
                const int u = blockIdx.x * (4 * R_A) + i * 4 + t;
                float iv = sigmoidf_(s_g[t][0]);
                float fv = sigmoidf_(s_g[t][1]);
                float gv = tanhf(s_g[t][2]);
                float ov = sigmoidf_(s_g[t][3]);
                float cn = fv * c0[u] + iv * gv;
                c0[u]     = cn;
                h0_out[u] = ov * tanhf(cn);
            }
            __syncthreads();
        }
    } else {
        // ----- layer 1: recurrent partials (Whh1 . h1_prev + biases) -----
        {
            float4 hv = ((const float4*)h1_in)[t];
            ((t & 1) ? s_a1 : s_a0)[t >> 1] = hv;
        }
        __syncthreads();
        const int bb = blockIdx.x - NB_A;
        #pragma unroll
        for (int i = 0; i < R_B; i++) {
            const int row = bb * (16 * R_B) + i * 16 + warp;
            float acc = rowdot16(Whh1, row, s_a0, s_a1, lane);
            #pragma unroll
            for (int o = 16; o > 0; o >>= 1)
                acc += __shfl_xor_sync(0xffffffffu, acc, o);
            if (lane == 0)
                pre1[row] = acc + bih1[row] + bhh1[row];
        }
    }
}

// ---------------------------------------------------------------------------
// K2: layer-1 input half + pointwise. Grid = 128 x 512, single wave.
// ---------------------------------------------------------------------------
__global__ void __launch_bounds__(512) step_k2(
    const __half* __restrict__ Wih1,
    const float* __restrict__ pre1,
    const float* __restrict__ h0_new,
    float* __restrict__ h1_out, float* __restrict__ c1)
{
    __shared__ float4 s_a0[256], s_a1[256];
    __shared__ float s_g[4][4];

    const int t    = threadIdx.x;
    const int warp = t >> 5;
    const int lane = t & 31;

    {
        float4 hv = ((const float4*)h0_new)[t];
        ((t & 1) ? s_a1 : s_a0)[t >> 1] = hv;
    }
    __syncthreads();

    const int ulocal = warp >> 2;
    const int gate   = warp & 3;

    #pragma unroll
    for (int i = 0; i < R_2; i++) {
        const int unit = blockIdx.x * (4 * R_2) + i * 4 + ulocal;
        const int row  = gate * HDIM + unit;
        float acc = rowdot16(Wih1, row, s_a0, s_a1, lane);
        #pragma unroll
        for (int o = 16; o > 0; o >>= 1)
            acc += __shfl_xor_sync(0xffffffffu, acc, o);
        if (lane == 0)
            s_g[ulocal][gate] = acc + pre1[row];
        __syncthreads();
        if (t < 4) {
            const int u = blockIdx.x * (4 * R_2) + i * 4 + t;
            float iv = sigmoidf_(s_g[t][0]);
            float fv = sigmoidf_(s_g[t][1]);
            float gv = tanhf(s_g[t][2]);
            float ov = sigmoidf_(s_g[t][3]);
            float cn = fv * c1[u] + iv * gv;
            c1[u]     = cn;
            h1_out[u] = ov * tanhf(cn);
        }
        __syncthreads();
    }
}

// ---------------------------------------------------------------------------
// K3: logits (fp16) + deterministic per-block exp-sum partials. 128 x 512.
// ---------------------------------------------------------------------------
__global__ void __launch_bounds__(512) logits_fp16(
    const __half* __restrict__ Wout,
    const float* __restrict__ bout,
    const float* __restrict__ h,
    float* __restrict__ logits,
    float* __restrict__ partials)
{
    __shared__ float4 s_h0[256], s_h1[256];
    __shared__ float s_e[16];

    const int t    = threadIdx.x;
    const int warp = t >> 5;
    const int lane = t & 31;

    {
        float4 hv = ((const float4*)h)[t];
        ((t & 1) ? s_h1 : s_h0)[t >> 1] = hv;
    }
    __syncthreads();

    const int row = blockIdx.x * 16 + warp;
    float acc = rowdot16(Wout, row, s_h0, s_h1, lane);
    #pragma unroll
    for (int o = 16; o > 0; o >>= 1)
        acc += __shfl_xor_sync(0xffffffffu, acc, o);
    if (lane == 0) {
        float lg = acc + bout[row];
        logits[row] = lg;
        s_e[warp] = __expf(lg);
    }
    __syncthreads();
    if (warp == 0) {
        float v = (lane < 16) ? s_e[lane] : 0.0f;
        #pragma unroll
        for (int o = 16; o > 0; o >>= 1)
            v += __shfl_xor_sync(0xffffffffu, v, o);
        if (lane == 0) partials[blockIdx.x] = v;
    }
}

// ---------------------------------------------------------------------------
// Step-0: fused fp32 compute + fp16 cache write. Grid = 128 x 512, R=4.
// ---------------------------------------------------------------------------
__global__ void __launch_bounds__(512) lstm_gates_cvt(
    const float* __restrict__ Wih32, const float* __restrict__ Whh32,
    __half* __restrict__ WihC, __half* __restrict__ WhhC,
    const float* __restrict__ bih, const float* __restrict__ bhh,
    const float* __restrict__ inp,
    const float* __restrict__ hin,
    float* __restrict__ hout,
    float* __restrict__ cio)
{
    __shared__ float4 s_in0[256], s_in1[256], s_h0[256], s_h1[256];
    __shared__ float s_g[4][4];

    const int t    = threadIdx.x;
    const int warp = t >> 5;
    const int lane = t & 31;

    {
        float4 v = ((const float4*)inp)[t];
        ((t & 1) ? s_in1 : s_in0)[t >> 1] = v;
        float4 hv = ((const float4*)hin)[t];
        ((t & 1) ? s_h1 : s_h0)[t >> 1] = hv;
    }
    __syncthreads();

    const int ulocal = warp >> 2;
    const int gate   = warp & 3;
    const float4* sel_in = (lane & 1) ? s_in1 : s_in0;
    const float4* sel_h  = (lane & 1) ? s_h1  : s_h0;

    for (int i = 0; i < R_A; i++) {
        const int unit = blockIdx.x * (4 * R_A) + i * 4 + ulocal;
        const int row  = gate * HDIM + unit;

        const float4* __restrict__ wi32 = (const float4*)Wih32 + (size_t)row * (HDIM / 4);
        const float4* __restrict__ wh32 = (const float4*)Whh32 + (size_t)row * (HDIM / 4);
        uint2* __restrict__ wiC = (uint2*)(WihC + (size_t)row * HDIM);
        uint2* __restrict__ whC = (uint2*)(WhhC + (size_t)row * HDIM);

        float acc0 = 0.f, acc1 = 0.f, acc2 = 0.f, acc3 = 0.f;
        #pragma unroll
        for (int j = 0; j < 16; j += 4) {
            float4 wv[4];
            #pragma unroll
            for (int jj = 0; jj < 4; jj++) wv[jj] = wi32[lane + (j + jj) * 32];
            #pragma unroll
            for (int jj = 0; jj < 4; jj++) {
                const int f = lane + (j + jj) * 32;
                __half2 p0 = __floats2half2_rn(wv[jj].x, wv[jj].y);
                __half2 p1 = __floats2half2_rn(wv[jj].z, wv[jj].w);
                uint2 st; st.x = *(unsigned*)&p0; st.y = *(unsigned*)&p1;
                wiC[f] = st;
                float4 a = sel_in[f >> 1];
                acc0 = fmaf(wv[jj].x, a.x, acc0); acc1 = fmaf(wv[jj].y, a.y, acc1);
                acc2 = fmaf(wv[jj].z, a.z, acc2); acc3 = fmaf(wv[jj].w, a.w, acc3);
            }
        }
        #pragma unroll
        for (int j = 0; j < 16; j += 4) {
            float4 wv[4];
            #pragma unroll
            for (int jj = 0; jj < 4; jj++) wv[jj] = wh32[lane + (j + jj) * 32];
            #pragma unroll
            for (int jj = 0; jj < 4; jj++) {
                const int f = lane + (j + jj) * 32;
                __half2 p0 = __floats2half2_rn(wv[jj].x, wv[jj].y);
                __half2 p1 = __floats2half2_rn(wv[jj].z, wv[jj].w);
                uint2 st; st.x = *(unsigned*)&p0; st.y = *(unsigned*)&p1;
                whC[f] = st;
                float4 a = sel_h[f >> 1];
                acc0 = fmaf(wv[jj].x, a.x, acc0); acc1 = fmaf(wv[jj].y, a.y, acc1);
                acc2 = fmaf(wv[jj].z, a.z, acc2); acc3 = fmaf(wv[jj].w, a.w, acc3);
            }
        }

        float acc = (acc0 + acc1) + (acc2 + acc3);
        #pragma unroll
        for (int o = 16; o > 0; o >>= 1)
            acc += __shfl_xor_sync(0xffffffffu, acc, o);
        if (lane == 0)
            s_g[ulocal][gate] = acc + bih[row] + bhh[row];
        __syncthreads();
        if (t < 4) {
            const int u = blockIdx.x * (4 * R_A) + i * 4 + t;
            float iv = sigmoidf_(s_g[t][0]);
            float fv = sigmoidf_(s_g[t][1]);
            float gv = tanhf(s_g[t][2]);
            float ov = sigmoidf_(s_g[t][3]);
            float cn = fv * cio[u] + iv * gv;
            cio[u]  = cn;
            hout[u] = ov * tanhf(cn);
        }
        __syncthreads();
    }
}

// Step-0 logits: fp32 weights + write fp16 cache. 128 x 512.
__global__ void __launch_bounds__(512) logits_cvt(
    const float* __restrict__ Wout32,
    __half* __restrict__ WoutC,
    const float* __restrict__ bout,
    const float* __restrict__ h,
    float* __restrict__ logits,
    float* __restrict__ partials)
{
    __shared__ float4 s_h0[256], s_h1[256];
    __shared__ float s_e[16];

    const int t    = threadIdx.x;
    const int warp = t >> 5;
    const int lane = t & 31;

    {
        float4 hv = ((const float4*)h)[t];
        ((t & 1) ? s_h1 : s_h0)[t >> 1] = hv;
    }
    __syncthreads();

    const int row = blockIdx.x * 16 + warp;
    const float4* __restrict__ w32 = (const float4*)Wout32 + (size_t)row * (HDIM / 4);
    uint2* __restrict__ wC = (uint2*)(WoutC + (size_t)row * HDIM);
    const float4* sel_h = (lane & 1) ? s_h1 : s_h0;

    float acc0 = 0.f, acc1 = 0.f, acc2 = 0.f, acc3 = 0.f;
    #pragma unroll
    for (int j = 0; j < 16; j += 4) {
        float4 wv[4];
        #pragma unroll
        for (int jj = 0; jj < 4; jj++) wv[jj] = w32[lane + (j + jj) * 32];
        #pragma unroll
        for (int jj = 0; jj < 4; jj++) {
            const int f = lane + (j + jj) * 32;
            __half2 p0 = __floats2half2_rn(wv[jj].x, wv[jj].y);
            __half2 p1 = __floats2half2_rn(wv[jj].z, wv[jj].w);
            uint2 st; st.x = *(unsigned*)&p0; st.y = *(unsigned*)&p1;
            wC[f] = st;
            float4 a = sel_h[f >> 1];
            acc0 = fmaf(wv[jj].x, a.x, acc0); acc1 = fmaf(wv[jj].y, a.y, acc1);
            acc2 = fmaf(wv[jj].z, a.z, acc2); acc3 = fmaf(wv[jj].w, a.w, acc3);
        }
    }

    float acc = (acc0 + acc1) + (acc2 + acc3);
    #pragma unroll
    for (int o = 16; o > 0; o >>= 1)
        acc += __shfl_xor_sync(0xffffffffu, acc, o);
    if (lane == 0) {
        float lg = acc + bout[row];
        logits[row] = lg;
        s_e[warp] = __expf(lg);
    }
    __syncthreads();
    if (warp == 0) {
        float v = (lane < 16) ? s_e[lane] : 0.0f;
        #pragma unroll
        for (int o = 16; o > 0; o >>= 1)
            v += __shfl_xor_sync(0xffffffffu, v, o);
        if (lane == 0) partials[blockIdx.x] = v;
    }
}

// Final step's softmax output row.
__global__ void __launch_bounds__(512) final_softmax_kernel(
    const float* __restrict__ logits,
    const float* __restrict__ partials,
    float* __restrict__ out_row)
{
    __shared__ float s_inv;
    const int t    = threadIdx.x;
    const int warp = t >> 5;
    const int lane = t & 31;
    if (warp == 0) {
        float s = 0.0f;
        #pragma unroll
        for (int j = 0; j < 4; j++) s += partials[lane + j * 32];
        #pragma unroll
        for (int o = 16; o > 0; o >>= 1)
            s += __shfl_xor_sync(0xffffffffu, s, o);
        if (lane == 0) s_inv = 1.0f / s;
    }
    __syncthreads();
    const float inv = s_inv;
    float4 lg = ((const float4*)logits)[t];
    float4 v;
    v.x = __expf(lg.x) * inv;
    v.y = __expf(lg.y) * inv;
    v.z = __expf(lg.z) * inv;
    v.w = __expf(lg.w) * inv;
    ((float4*)out_row)[t] = v;
}

// ---------------------------------------------------------------------------
extern "C" void kernel_launch(void* const* d_in, const int* in_sizes, int n_in,
                              void* d_out, int out_size)
{
    const float* x    = (const float*)d_in[0];
    const float* Wih  = (const float*)d_in[1];
    const float* Whh  = (const float*)d_in[2];
    const float* bih  = (const float*)d_in[3];
    const float* bhh  = (const float*)d_in[4];
    const float* Wout = (const float*)d_in[5];
    const float* bout = (const float*)d_in[6];
    float* out = (float*)d_out;

    float *h0, *h1, *cbuf, *gl, *gp, *pre1;
    __half *wih16, *whh16, *wout16;
    cudaGetSymbolAddress((void**)&h0,     g_h0);
    cudaGetSymbolAddress((void**)&h1,     g_h1);
    cudaGetSymbolAddress((void**)&cbuf,   g_c);
    cudaGetSymbolAddress((void**)&gl,     g_logits);
    cudaGetSymbolAddress((void**)&gp,     g_partial);
    cudaGetSymbolAddress((void**)&pre1,   g_pre1);
    cudaGetSymbolAddress((void**)&wih16,  g_wih16);
    cudaGetSymbolAddress((void**)&whh16,  g_whh16);
    cudaGetSymbolAddress((void**)&wout16, g_wout16);

    // zero h0[0], h1[0], c
    cudaMemsetAsync(h0, 0, sizeof(float) * HDIM);
    cudaMemsetAsync(h1, 0, sizeof(float) * HDIM);
    cudaMemsetAsync(cbuf, 0, sizeof(float) * LNUM * HDIM);

    const size_t wOffL = (size_t)4 * HDIM * HDIM;
    const size_t bOffL = (size_t)4 * HDIM;

    // ---- step 0: fp32 fused compute + fp16 cache ----
    lstm_gates_cvt<<<NB_A, 512>>>(
        Wih, Whh, wih16, whh16, bih, bhh,
        x, h0 /*h0[0]=0*/, h0 + HDIM /*h0[1]*/, cbuf);
    lstm_gates_cvt<<<NB_A, 512>>>(
        Wih + wOffL, Whh + wOffL, wih16 + wOffL, whh16 + wOffL,
        bih + bOffL, bhh + bOffL,
        h0 + HDIM, h1 /*h1[0]=0*/, h1 + HDIM /*h1[1]*/, cbuf + HDIM);
    logits_cvt<<<NLOGBLK, 512>>>(Wout, wout16, bout, h1 + HDIM, gl, gp);

    // ---- steps 1..A-1 ----
    for (int s = 1; s < ANUM; s++) {
        const int r = s & 1;        // read index
        const int w = 1 - r;        // write index

        step_k1<<<NB_A + NB_B, 512>>>(
            wih16, whh16, whh16 + wOffL,
            bih, bhh, bih + bOffL, bhh + bOffL,
            gl, gp, out + (size_t)(s - 1) * SDIM,
            h0 + (size_t)r * HDIM, h0 + (size_t)w * HDIM,
            h1 + (size_t)r * HDIM,
            cbuf, pre1);
        step_k2<<<NB_A, 512>>>(
            wih16 + wOffL, pre1,
            h0 + (size_t)w * HDIM,
            h1 + (size_t)w * HDIM, cbuf + HDIM);
        logits_fp16<<<NLOGBLK, 512>>>(
            wout16, bout, h1 + (size_t)w * HDIM, gl, gp);
    }

    final_softmax_kernel<<<1, 512>>>(gl, gp, out + (size_t)(ANUM - 1) * SDIM);
}

// round 7
// speedup vs baseline: 1.2158x; 1.2158x over previous
#include <cuda_runtime.h>
#include <cuda_fp16.h>
#include <cstdint>
#include <math.h>

#define SDIM 2048
#define HDIM 2048
#define ANUM 16
#define NB_A 256      // K1 type-A blocks (layer0 gates, 8 units each)
#define NB_B 256      // K1 type-B blocks (layer1 recurrent, 32 rows each)
#define CH   8        // chunks per row (2048 / 256)
#define CC   256      // halfs per chunk per row per matrix
#define NSTG 3        // pipeline stages

// Persistent scratch
__device__ __align__(16) float g_h0[2][HDIM];
__device__ __align__(16) float g_h1[2][HDIM];
__device__ __align__(16) float g_c[2][HDIM];
__device__ __align__(16) float g_pre1[4 * HDIM];
__device__ __align__(16) float g_logits[SDIM];
__device__ __align__(16) float g_partial[128];
__device__ __align__(16) __half g_wih16[2 * 4 * HDIM * HDIM];
__device__ __align__(16) __half g_whh16[2 * 4 * HDIM * HDIM];
__device__ __align__(16) __half g_wout16[SDIM * HDIM];

__device__ __forceinline__ float sigmoidf_(float x) {
    return 1.0f / (1.0f + __expf(-x));
}

__device__ __forceinline__ void cp16(uint32_t dst, const void* src) {
    asm volatile("cp.async.cg.shared.global [%0], [%1], 16;"
                 :: "r"(dst), "l"(src) : "memory");
}
#define CP_COMMIT() asm volatile("cp.async.commit_group;" ::: "memory")
#define CP_WAIT1()  asm volatile("cp.async.wait_group 1;"  ::: "memory")

// 8 half-weights (uint4) dot 8 floats (two float4), into two accumulators.
__device__ __forceinline__ void dot8(uint4 w, float4 lo, float4 hi,
                                     float& p, float& q) {
    const __half2* hp = reinterpret_cast<const __half2*>(&w);
    float2 f0 = __half22float2(hp[0]);
    float2 f1 = __half22float2(hp[1]);
    float2 f2 = __half22float2(hp[2]);
    float2 f3 = __half22float2(hp[3]);
    p = fmaf(f0.x, lo.x, p); q = fmaf(f0.y, lo.y, q);
    p = fmaf(f1.x, lo.z, p); q = fmaf(f1.y, lo.w, q);
    p = fmaf(f2.x, hi.x, p); q = fmaf(f2.y, hi.y, q);
    p = fmaf(f3.x, hi.z, p); q = fmaf(f3.y, hi.w, q);
}

// ===========================================================================
// K1: type-A blocks = layer-0 full gates (+inline softmax input, step>0);
//     type-B blocks = layer-1 recurrent partials -> pre1.
// 512 threads, 2 rows/warp. Per-warp private cp.async pipeline, no barriers
// in the streaming loop.
// Dynamic smem: act 16 KB (sIn0/1, sH0/1) + 16 warps * 6 KB tiles = 112 KB.
// ===========================================================================
template<int FIRST>
__global__ void __launch_bounds__(512, 2) step_k1(
    const __half* __restrict__ Wih0, const __half* __restrict__ Whh0,
    const __half* __restrict__ Whh1,
    const float* __restrict__ bih0, const float* __restrict__ bhh0,
    const float* __restrict__ bih1, const float* __restrict__ bhh1,
    const float* __restrict__ xin,
    const float* __restrict__ logits, const float* __restrict__ partials,
    float* __restrict__ out_prev,
    const float* __restrict__ h0_in, float* __restrict__ h0_out,
    const float* __restrict__ h1_in,
    float* __restrict__ c0, float* __restrict__ pre1)
{
    extern __shared__ __align__(16) char smem[];
    float4* sIn0 = (float4*)smem;          // even float4s of input vec
    float4* sIn1 = sIn0 + 256;             // odd
    float4* sH0  = sIn1 + 256;
    float4* sH1  = sH0 + 256;
    __half* tiles = (__half*)(smem + 16384);
    __shared__ float s_g[32];
    __shared__ float s_inv;

    const int t = threadIdx.x, warp = t >> 5, lane = t & 31;
    const bool typeA = (blockIdx.x < NB_A);
    const uint32_t smemU = (uint32_t)__cvta_generic_to_shared(smem);
    const uint32_t tileU = smemU + 16384 + warp * 6144 + lane * 16;
    const __half* tileh  = tiles + warp * 3072;

    // Row pointers (rg1 = rg0 + 1 always, both block types).
    int rg0;
    const __half *rA0, *rB0;
    if (typeA) {
        const int i0 = 2 * warp;                       // in-block row 0..31
        rg0 = (i0 >> 3) * HDIM + blockIdx.x * 8 + (i0 & 7);
        rA0 = Wih0 + (size_t)rg0 * HDIM;
        rB0 = Whh0 + (size_t)rg0 * HDIM;
    } else {
        rg0 = (blockIdx.x - NB_A) * 32 + 2 * warp;
        rA0 = Whh1 + (size_t)rg0 * HDIM;
        rB0 = nullptr;
    }

    // ---- prologue: start streaming chunks 0..NSTG-2 immediately ----
    if (typeA) {
        #pragma unroll
        for (int s = 0; s < NSTG - 1; s++) {
            const uint32_t d = tileU + s * 2048;
            cp16(d,        rA0 + s * CC + lane * 8);
            cp16(d + 512,  rA0 + HDIM + s * CC + lane * 8);
            cp16(d + 1024, rB0 + s * CC + lane * 8);
            cp16(d + 1536, rB0 + HDIM + s * CC + lane * 8);
            CP_COMMIT();
        }
    } else {
        #pragma unroll
        for (int s = 0; s < NSTG - 1; s++) {
            const uint32_t d = tileU + s * 2048;
            cp16(d,       rA0 + s * CC + lane * 8);
            cp16(d + 512, rA0 + HDIM + s * CC + lane * 8);
            CP_COMMIT();
        }
    }

    // ---- stage activations (overlaps with cp.async fetch latency) ----
    if (typeA) {
        if (!FIRST) {
            if (warp == 0) {
                float s = partials[lane] + partials[lane + 32]
                        + partials[lane + 64] + partials[lane + 96];
                #pragma unroll
                for (int o = 16; o > 0; o >>= 1)
                    s += __shfl_xor_sync(0xffffffffu, s, o);
                if (lane == 0) s_inv = 1.0f / s;
            }
            __syncthreads();
        }
        float4 v;
        if (FIRST) {
            v = ((const float4*)xin)[t];
        } else {
            float4 lg = ((const float4*)logits)[t];
            const float inv = s_inv;
            v.x = __expf(lg.x) * inv;
            v.y = __expf(lg.y) * inv;
            v.z = __expf(lg.z) * inv;
            v.w = __expf(lg.w) * inv;
            if (blockIdx.x == 0) ((float4*)out_prev)[t] = v;
        }
        ((t & 1) ? sIn1 : sIn0)[t >> 1] = v;
        float4 hv = ((const float4*)h0_in)[t];
        ((t & 1) ? sH1 : sH0)[t >> 1] = hv;
    } else {
        float4 hv = ((const float4*)h1_in)[t];
        ((t & 1) ? sIn1 : sIn0)[t >> 1] = hv;
    }
    __syncthreads();

    // ---- barrier-free streaming loop ----
    float p0 = 0.f, q0 = 0.f, p1 = 0.f, q1 = 0.f;
    if (typeA) {
        #pragma unroll
        for (int c = 0; c < CH; c++) {
            CP_WAIT1();
            const int st = c % NSTG;
            const float4 a0 = sIn0[c * 32 + lane], a1 = sIn1[c * 32 + lane];
            const float4 b0 = sH0[c * 32 + lane],  b1 = sH1[c * 32 + lane];
            const __half* tp = tileh + st * 1024;
            uint4 wA0 = *(const uint4*)(tp +       lane * 8);
            uint4 wA1 = *(const uint4*)(tp + 256 + lane * 8);
            uint4 wB0 = *(const uint4*)(tp + 512 + lane * 8);
            uint4 wB1 = *(const uint4*)(tp + 768 + lane * 8);
            dot8(wA0, a0, a1, p0, q0);
            dot8(wB0, b0, b1, p0, q0);
            dot8(wA1, a0, a1, p1, q1);
            dot8(wB1, b0, b1, p1, q1);
            const int nc = c + NSTG - 1;
            if (nc < CH) {
                const uint32_t d = tileU + (nc % NSTG) * 2048;
                cp16(d,        rA0 + nc * CC + lane * 8);
                cp16(d + 512,  rA0 + HDIM + nc * CC + lane * 8);
                cp16(d + 1024, rB0 + nc * CC + lane * 8);
                cp16(d + 1536, rB0 + HDIM + nc * CC + lane * 8);
            }
            CP_COMMIT();
        }
    } else {
        #pragma unroll
        for (int c = 0; c < CH; c++) {
            CP_WAIT1();
            const int st = c % NSTG;
            const float4 a0 = sIn0[c * 32 + lane], a1 = sIn1[c * 32 + lane];
            const __half* tp = tileh + st * 1024;
            uint4 wA0 = *(const uint4*)(tp +       lane * 8);
            uint4 wA1 = *(const uint4*)(tp + 256 + lane * 8);
            dot8(wA0, a0, a1, p0, q0);
            dot8(wA1, a0, a1, p1, q1);
            const int nc = c + NSTG - 1;
            if (nc < CH) {
                const uint32_t d = tileU + (nc % NSTG) * 2048;
                cp16(d,       rA0 + nc * CC + lane * 8);
                cp16(d + 512, rA0 + HDIM + nc * CC + lane * 8);
            }
            CP_COMMIT();
        }
    }

    // ---- reduce + epilogue ----
    float v0 = p0 + q0, v1 = p1 + q1;
    #pragma unroll
    for (int o = 16; o > 0; o >>= 1) {
        v0 += __shfl_xor_sync(0xffffffffu, v0, o);
        v1 += __shfl_xor_sync(0xffffffffu, v1, o);
    }
    if (typeA) {
        if (lane == 0) {
            s_g[2 * warp]     = v0 + bih0[rg0] + bhh0[rg0];
            s_g[2 * warp + 1] = v1 + bih0[rg0 + 1] + bhh0[rg0 + 1];
        }
        __syncthreads();
        if (t < 8) {
            const int u = blockIdx.x * 8 + t;
            float iv = sigmoidf_(s_g[t]);
            float fv = sigmoidf_(s_g[8 + t]);
            float gv = tanhf(s_g[16 + t]);
            float ov = sigmoidf_(s_g[24 + t]);
            float cn = fv * c0[u] + iv * gv;
            c0[u]     = cn;
            h0_out[u] = ov * tanhf(cn);
        }
    } else {
        if (lane == 0) {
            pre1[rg0]     = v0 + bih1[rg0] + bhh1[rg0];
            pre1[rg0 + 1] = v1 + bih1[rg0 + 1] + bhh1[rg0 + 1];
        }
    }
}

// ===========================================================================
// K2: layer-1 input half (Wih1) + pointwise. 256 blocks (8 units each),
// 2 rows/warp, single matrix. Dyn smem: 8 KB act + 16 * 3 KB = 56 KB.
// ===========================================================================
__global__ void __launch_bounds__(512, 2) step_k2(
    const __half* __restrict__ Wih1,
    const float* __restrict__ pre1,
    const float* __restrict__ h0_new,
    float* __restrict__ h1_out, float* __restrict__ c1)
{
    extern __shared__ __align__(16) char smem[];
    float4* sA0 = (float4*)smem;
    float4* sA1 = sA0 + 256;
    __half* tiles = (__half*)(smem + 8192);
    __shared__ float s_g[32];

    const int t = threadIdx.x, warp = t >> 5, lane = t & 31;
    const uint32_t smemU = (uint32_t)__cvta_generic_to_shared(smem);
    const uint32_t tileU = smemU + 8192 + warp * 3072 + lane * 16;
    const __half* tileh  = tiles + warp * 1536;

    const int i0 = 2 * warp;
    const int rg0 = (i0 >> 3) * HDIM + blockIdx.x * 8 + (i0 & 7);
    const __half* rA0 = Wih1 + (size_t)rg0 * HDIM;

    #pragma unroll
    for (int s = 0; s < NSTG - 1; s++) {
        const uint32_t d = tileU + s * 1024;
        cp16(d,       rA0 + s * CC + lane * 8);
        cp16(d + 512, rA0 + HDIM + s * CC + lane * 8);
        CP_COMMIT();
    }

    {
        float4 hv = ((const float4*)h0_new)[t];
        ((t & 1) ? sA1 : sA0)[t >> 1] = hv;
    }
    __syncthreads();

    float p0 = 0.f, q0 = 0.f, p1 = 0.f, q1 = 0.f;
    #pragma unroll
    for (int c = 0; c < CH; c++) {
        CP_WAIT1();
        const int st = c % NSTG;
        const float4 a0 = sA0[c * 32 + lane], a1 = sA1[c * 32 + lane];
        const __half* tp = tileh + st * 512;
        uint4 w0 = *(const uint4*)(tp +       lane * 8);
        uint4 w1 = *(const uint4*)(tp + 256 + lane * 8);
        dot8(w0, a0, a1, p0, q0);
        dot8(w1, a0, a1, p1, q1);
        const int nc = c + NSTG - 1;
        if (nc < CH) {
            const uint32_t d = tileU + (nc % NSTG) * 1024;
            cp16(d,       rA0 + nc * CC + lane * 8);
            cp16(d + 512, rA0 + HDIM + nc * CC + lane * 8);
        }
        CP_COMMIT();
    }

    float v0 = p0 + q0, v1 = p1 + q1;
    #pragma unroll
    for (int o = 16; o > 0; o >>= 1) {
        v0 += __shfl_xor_sync(0xffffffffu, v0, o);
        v1 += __shfl_xor_sync(0xffffffffu, v1, o);
    }
    if (lane == 0) {
        s_g[2 * warp]     = v0 + pre1[rg0];
        s_g[2 * warp + 1] = v1 + pre1[rg0 + 1];
    }
    __syncthreads();
    if (t < 8) {
        const int u = blockIdx.x * 8 + t;
        float iv = sigmoidf_(s_g[t]);
        float fv = sigmoidf_(s_g[8 + t]);
        float gv = tanhf(s_g[16 + t]);
        float ov = sigmoidf_(s_g[24 + t]);
        float cn = fv * c1[u] + iv * gv;
        c1[u]     = cn;
        h1_out[u] = ov * tanhf(cn);
    }
}

// ===========================================================================
// K3: logits + deterministic per-block exp-sum partials. 128 blocks,
// 1 row/warp. Dyn smem: 8 KB act + 16 * 1.5 KB = 32 KB.
// ===========================================================================
__global__ void __launch_bounds__(512, 2) step_k3(
    const __half* __restrict__ Wout,
    const float* __restrict__ bout,
    const float* __restrict__ h,
    float* __restrict__ logits,
    float* __restrict__ partials)
{
    extern __shared__ __align__(16) char smem[];
    float4* sA0 = (float4*)smem;
    float4* sA1 = sA0 + 256;
    __half* tiles = (__half*)(smem + 8192);
    __shared__ float s_e[16];

    const int t = threadIdx.x, warp = t >> 5, lane = t & 31;
    const uint32_t smemU = (uint32_t)__cvta_generic_to_shared(smem);
    const uint32_t tileU = smemU + 8192 + warp * 1536 + lane * 16;
    const __half* tileh  = tiles + warp * 768;

    const int row = blockIdx.x * 16 + warp;
    const __half* rA = Wout + (size_t)row * HDIM;

    #pragma unroll
    for (int s = 0; s < NSTG - 1; s++) {
        cp16(tileU + s * 512, rA + s * CC + lane * 8);
        CP_COMMIT();
    }

    {
        float4 hv = ((const float4*)h)[t];
        ((t & 1) ? sA1 : sA0)[t >> 1] = hv;
    }
    __syncthreads();

    float p = 0.f, q = 0.f;
    #pragma unroll
    for (int c = 0; c < CH; c++) {
        CP_WAIT1();
        const int st = c % NSTG;
        const float4 a0 = sA0[c * 32 + lane], a1 = sA1[c * 32 + lane];
        uint4 w = *(const uint4*)(tileh + st * 256 + lane * 8);
        dot8(w, a0, a1, p, q);
        const int nc = c + NSTG - 1;
        if (nc < CH)
            cp16(tileU + (nc % NSTG) * 512, rA + nc * CC + lane * 8);
        CP_COMMIT();
    }

    float v = p + q;
    #pragma unroll
    for (int o = 16; o > 0; o >>= 1)
        v += __shfl_xor_sync(0xffffffffu, v, o);
    if (lane == 0) {
        float lg = v + bout[row];
        logits[row] = lg;
        s_e[warp] = __expf(lg);
    }
    __syncthreads();
    if (warp == 0) {
        float s = (lane < 16) ? s_e[lane] : 0.0f;
        #pragma unroll
        for (int o = 16; o > 0; o >>= 1)
            s += __shfl_xor_sync(0xffffffffu, s, o);
        if (lane == 0) partials[blockIdx.x] = s;
    }
}

// ===========================================================================
// One-shot fp32 -> fp16 conversion over all three weight arrays.
// ===========================================================================
__global__ void __launch_bounds__(256) cvt_all(
    const float* __restrict__ a, __half* __restrict__ da, int na,
    const float* __restrict__ b, __half* __restrict__ db, int nb,
    const float* __restrict__ c, __half* __restrict__ dc, int ncnt)
{
    const int total = (na + nb + ncnt) >> 3;
    const int stride = gridDim.x * blockDim.x;
    for (int u = blockIdx.x * blockDim.x + threadIdx.x; u < total; u += stride) {
        const int i = u << 3;
        const float* s; __half* d;
        if (i < na)            { s = a + i;            d = da + i; }
        else if (i < na + nb)  { s = b + (i - na);     d = db + (i - na); }
        else                   { s = c + (i - na - nb); d = dc + (i - na - nb); }
        float4 x0 = *(const float4*)s;
        float4 x1 = *(const float4*)(s + 4);
        __half2 h0 = __floats2half2_rn(x0.x, x0.y);
        __half2 h1 = __floats2half2_rn(x0.z, x0.w);
        __half2 h2 = __floats2half2_rn(x1.x, x1.y);
        __half2 h3 = __floats2half2_rn(x1.z, x1.w);
        uint4 o;
        o.x = *(unsigned*)&h0; o.y = *(unsigned*)&h1;
        o.z = *(unsigned*)&h2; o.w = *(unsigned*)&h3;
        *(uint4*)d = o;
    }
}

// Final step's softmax output row.
__global__ void __launch_bounds__(512) final_softmax_kernel(
    const float* __restrict__ logits,
    const float* __restrict__ partials,
    float* __restrict__ out_row)
{
    __shared__ float s_inv;
    const int t = threadIdx.x, warp = t >> 5, lane = t & 31;
    if (warp == 0) {
        float s = partials[lane] + partials[lane + 32]
                + partials[lane + 64] + partials[lane + 96];
        #pragma unroll
        for (int o = 16; o > 0; o >>= 1)
            s += __shfl_xor_sync(0xffffffffu, s, o);
        if (lane == 0) s_inv = 1.0f / s;
    }
    __syncthreads();
    const float inv = s_inv;
    float4 lg = ((const float4*)logits)[t];
    float4 v;
    v.x = __expf(lg.x) * inv;
    v.y = __expf(lg.y) * inv;
    v.z = __expf(lg.z) * inv;
    v.w = __expf(lg.w) * inv;
    ((float4*)out_row)[t] = v;
}

// ---------------------------------------------------------------------------
extern "C" void kernel_launch(void* const* d_in, const int* in_sizes, int n_in,
                              void* d_out, int out_size)
{
    const float* x    = (const float*)d_in[0];
    const float* Wih  = (const float*)d_in[1];
    const float* Whh  = (const float*)d_in[2];
    const float* bih  = (const float*)d_in[3];
    const float* bhh  = (const float*)d_in[4];
    const float* Wout = (const float*)d_in[5];
    const float* bout = (const float*)d_in[6];
    float* out = (float*)d_out;

    float *h0, *h1, *cbuf, *gl, *gp, *pre1;
    __half *wih16, *whh16, *wout16;
    cudaGetSymbolAddress((void**)&h0,     g_h0);
    cudaGetSymbolAddress((void**)&h1,     g_h1);
    cudaGetSymbolAddress((void**)&cbuf,   g_c);
    cudaGetSymbolAddress((void**)&gl,     g_logits);
    cudaGetSymbolAddress((void**)&gp,     g_partial);
    cudaGetSymbolAddress((void**)&pre1,   g_pre1);
    cudaGetSymbolAddress((void**)&wih16,  g_wih16);
    cudaGetSymbolAddress((void**)&whh16,  g_whh16);
    cudaGetSymbolAddress((void**)&wout16, g_wout16);

    const int SM_K1 = 16384 + 16 * 6144;   // 114688
    const int SM_K2 = 8192 + 16 * 3072;    // 57344
    const int SM_K3 = 8192 + 16 * 1536;    // 32768
    cudaFuncSetAttribute(step_k1<0>, cudaFuncAttributeMaxDynamicSharedMemorySize, SM_K1);
    cudaFuncSetAttribute(step_k1<1>, cudaFuncAttributeMaxDynamicSharedMemorySize, SM_K1);
    cudaFuncSetAttribute(step_k2,    cudaFuncAttributeMaxDynamicSharedMemorySize, SM_K2);
    cudaFuncSetAttribute(step_k3,    cudaFuncAttributeMaxDynamicSharedMemorySize, SM_K3);

    cudaMemsetAsync(h0, 0, sizeof(float) * HDIM);           // h0[0]
    cudaMemsetAsync(h1, 0, sizeof(float) * HDIM);           // h1[0]
    cudaMemsetAsync(cbuf, 0, sizeof(float) * 2 * HDIM);     // c0, c1

    const int NW = 2 * 4 * HDIM * HDIM;   // 33.5M per matrix set
    const int NO = SDIM * HDIM;           // 4.2M
    cvt_all<<<2048, 256>>>(Wih, wih16, NW, Whh, whh16, NW, Wout, wout16, NO);

    const size_t wOffL = (size_t)4 * HDIM * HDIM;
    const size_t bOffL = (size_t)4 * HDIM;

    for (int s = 0; s < ANUM; s++) {
        const int r = s & 1;
        const int w = 1 - r;
        float* h0_in  = h0 + (size_t)r * HDIM;
        float* h0_out = h0 + (size_t)w * HDIM;
        float* h1_in  = h1 + (size_t)r * HDIM;
        float* h1_out = h1 + (size_t)w * HDIM;

        if (s == 0) {
            step_k1<1><<<NB_A + NB_B, 512, SM_K1>>>(
                wih16, whh16, whh16 + wOffL,
                bih, bhh, bih + bOffL, bhh + bOffL,
                x, nullptr, nullptr, nullptr,
                h0_in, h0_out, h1_in, cbuf, pre1);
        } else {
            step_k1<0><<<NB_A + NB_B, 512, SM_K1>>>(
                wih16, whh16, whh16 + wOffL,
                bih, bhh, bih + bOffL, bhh + bOffL,
                nullptr, gl, gp, out + (size_t)(s - 1) * SDIM,
                h0_in, h0_out, h1_in, cbuf, pre1);
        }
        step_k2<<<NB_A, 512, SM_K2>>>(
            wih16 + wOffL, pre1, h0_out, h1_out, cbuf + HDIM);
        step_k3<<<128, 512, SM_K3>>>(
            wout16, bout, h1_out, gl, gp);
    }

    final_softmax_kernel<<<1, 512>>>(gl, gp, out + (size_t)(ANUM - 1) * SDIM);
}